// round 5
// baseline (speedup 1.0000x reference)
#include <cuda_runtime.h>
#include <math.h>

// Dims
#define BB 16
#define NCO 64
#define NT 16
#define NHW 1024

// ---------------- persistent scratch (device globals; no allocation) -------
__device__ float g_h [BB*NCO*NHW];     // attended h (recurrent carry)   4 MB
__device__ float g_hg[BB*NCO*NHW];     // pre-attention h (gate output)  4 MB
__device__ float g_c [BB*NCO*NHW];     // cell state                     4 MB
__device__ float g_q [BB*16*NHW];      //  1 MB
__device__ float g_k [BB*16*NHW];      //  1 MB
__device__ float g_v [BB*NCO*NHW];     //  4 MB

// ---------------- init: zero h and c ---------------------------------------
__global__ void k_init()
{
    int i = blockIdx.x * 256 + threadIdx.x;
    g_h[i] = 0.f;
    g_c[i] = 0.f;
}

__device__ __forceinline__ float sigf(float x) { return 1.f / (1.f + __expf(-x)); }
__device__ __forceinline__ float tanh_fast(float x)
{
    return __fdividef(2.f, 1.f + __expf(-2.f * x)) - 1.f;
}

// ---------------- conv 3x3 + ConvLSTM gating fused -------------------------
// grid (16 chan-groups of 4, 16 batch), 256 threads.
__global__ void __launch_bounds__(256, 2) k_convgate(
    const float* __restrict__ X,   const float* __restrict__ Wc,
    const float* __restrict__ bc,
    const float* __restrict__ Wci, const float* __restrict__ Wcf,
    const float* __restrict__ Wco, int t)
{
    __shared__ float in_s[4 * 34 * 37];   // 4 ci, 34 rows, stride 37 (20.1 KB)
    __shared__ float w_s[16 * 36];        // 16 co x 4 ci x 9           (2.3 KB)

    const int b   = blockIdx.y;
    const int ch0 = blockIdx.x * 4;
    const int tid = threadIdx.x;
    const int y   = tid >> 3;            // 0..31
    const int x4  = (tid & 7) << 2;      // 0,4,...,28

    float acc[16][4];
    #pragma unroll
    for (int j = 0; j < 16; ++j)
        #pragma unroll
        for (int p = 0; p < 4; ++p) acc[j][p] = 0.f;

    for (int ch = 0; ch < 32; ++ch) {            // 32 chunks of 4 input ch.
        for (int i = tid; i < 576; i += 256) {
            int j = i / 36; int r = i - j * 36;
            int cog = ((j >> 2) << 6) + ch0 + (j & 3);
            w_s[i] = Wc[(cog * 128 + (ch * 4 + r / 9)) * 9 + (r % 9)];
        }
        for (int i = tid; i < 4 * 1156; i += 256) {
            int cc = i / 1156; int r = i - cc * 1156;
            int yy = r / 34;   int xx = r - yy * 34;
            int iy = yy - 1,   ix = xx - 1;
            int ci = ch * 4 + cc;
            const float* src = (ci < 64)
                ? (X + ((b * 64 + ci) * 16 + t) * 1024)
                : (g_h + (b * 64 + (ci - 64)) * 1024);
            float v = 0.f;
            if (iy >= 0 && iy < 32 && ix >= 0 && ix < 32) v = src[iy * 32 + ix];
            in_s[cc * 1258 + yy * 37 + xx] = v;
        }
        __syncthreads();

        #pragma unroll
        for (int cc = 0; cc < 4; ++cc) {
            float v[3][6];
            #pragma unroll
            for (int dy = 0; dy < 3; ++dy)
                #pragma unroll
                for (int dx = 0; dx < 6; ++dx)
                    v[dy][dx] = in_s[cc * 1258 + (y + dy) * 37 + (x4 + dx)];
            #pragma unroll
            for (int j = 0; j < 16; ++j) {
                const float* wp = &w_s[j * 36 + cc * 9];
                float w0 = wp[0], w1 = wp[1], w2 = wp[2];
                float w3 = wp[3], w4 = wp[4], w5 = wp[5];
                float w6 = wp[6], w7 = wp[7], w8 = wp[8];
                #pragma unroll
                for (int p = 0; p < 4; ++p) {
                    acc[j][p] += w0 * v[0][p] + w1 * v[0][p + 1] + w2 * v[0][p + 2]
                               + w3 * v[1][p] + w4 * v[1][p + 1] + w5 * v[1][p + 2]
                               + w6 * v[2][p] + w7 * v[2][p + 1] + w8 * v[2][p + 2];
                }
            }
        }
        __syncthreads();
    }

    #pragma unroll
    for (int cl = 0; cl < 4; ++cl) {
        int ch = ch0 + cl;
        float bi = bc[ch], bf = bc[64 + ch], bg = bc[128 + ch], bo = bc[192 + ch];
        #pragma unroll
        for (int p = 0; p < 4; ++p) {
            int pos = y * 32 + x4 + p;
            int idx = (b * 64 + ch) * 1024 + pos;
            int wpp = ch * 1024 + pos;
            float cp = g_c[idx];
            float ii = sigf(acc[cl][p]      + bi + Wci[wpp] * cp);
            float ff = sigf(acc[4 + cl][p]  + bf + Wcf[wpp] * cp);
            float nc = ff * cp + ii * tanh_fast(acc[8 + cl][p] + bg);
            float oo = sigf(acc[12 + cl][p] + bo + Wco[wpp] * nc);
            g_c[idx]  = nc;
            g_hg[idx] = oo * tanh_fast(nc);
        }
    }
}

// ---------------- q,k,v 1x1 convs: 96 output ch from 64 --------------------
__global__ void k_qkv(const float* __restrict__ qw, const float* __restrict__ qb,
                      const float* __restrict__ kw, const float* __restrict__ kb,
                      const float* __restrict__ vw, const float* __restrict__ vb)
{
    __shared__ float h_s[32 * 256];
    __shared__ float w_s[8 * 64];

    const int p0  = blockIdx.x * 256;
    const int oc0 = blockIdx.y * 8;
    const int b   = blockIdx.z;
    const int tid = threadIdx.x;

    for (int i = tid; i < 512; i += 256) {
        int j = i >> 6; int c = i & 63; int oc = oc0 + j;
        w_s[i] = (oc < 16) ? qw[oc * 64 + c]
               : (oc < 32) ? kw[(oc - 16) * 64 + c]
                           : vw[(oc - 32) * 64 + c];
    }

    float acc[8];
    #pragma unroll
    for (int j = 0; j < 8; ++j) {
        int oc = oc0 + j;
        acc[j] = (oc < 16) ? qb[oc] : (oc < 32) ? kb[oc - 16] : vb[oc - 32];
    }

    for (int chh = 0; chh < 2; ++chh) {
        __syncthreads();
        for (int i = tid; i < 8192; i += 256) {
            int c = i >> 8; int j = i & 255;
            h_s[i] = g_hg[(b * 64 + chh * 32 + c) * 1024 + p0 + j];
        }
        __syncthreads();
        #pragma unroll 8
        for (int c = 0; c < 32; ++c) {
            float hv = h_s[c * 256 + tid];
            #pragma unroll
            for (int j = 0; j < 8; ++j)
                acc[j] += w_s[j * 64 + chh * 32 + c] * hv;
        }
    }

    int pos = p0 + tid;
    #pragma unroll
    for (int j = 0; j < 8; ++j) {
        int oc = oc0 + j;
        if (oc < 16)      g_q[(b * 16 + oc) * 1024 + pos]        = acc[j];
        else if (oc < 32) g_k[(b * 16 + (oc - 16)) * 1024 + pos] = acc[j];
        else              g_v[(b * 64 + (oc - 32)) * 1024 + pos] = acc[j];
    }
}

// ---------------- fused attention: scores+softmax+P@v^T+z_w+write ----------
// grid (64 row-groups of 16, 16 batch), 256 threads = 8 warps.
// Phase A: warp = 2 rows, k staged TRANSPOSED [m][c] -> 4 LDS.128 per 32 FFMA.
// Phase C: thread = 4 channels x 4 rows x quarter-of-m (16 accs, 2 B/FFMA
// from smem), partials reduced once through smem at the end.
__global__ void __launch_bounds__(256, 2) k_attn(
    const float* __restrict__ zw, const float* __restrict__ zb,
    float* __restrict__ out, int t)
{
    __shared__ float smem[12288];            // 48 KB exactly
    float* z_s = smem;                       // [64][20] = 1280, persists C->D
    float* u_s = smem + 1280;                // 11008-float staging union
    float* P_s = u_s;                        // phase C: [128][20] = 2560
    float* v_s = u_s + 2560;                 // phase C: [64][132] = 8448

    const int b    = blockIdx.y;
    const int n0b  = blockIdx.x * 16;
    const int tid  = threadIdx.x;
    const int w    = tid >> 5;
    const int lane = tid & 31;
    const int rl   = w * 2;                  // this warp's first local row
    const int r0   = n0b + rl;

    // ---- phase A: scores s[32] per row; k transposed in smem --------------
    float q0[16], q1[16];
    #pragma unroll
    for (int c = 0; c < 16; ++c) {
        q0[c] = g_q[(b * 16 + c) * 1024 + r0];
        q1[c] = g_q[(b * 16 + c) * 1024 + r0 + 1];
    }

    float s0[32], s1[32];
    for (int chh = 0; chh < 4; ++chh) {
        __syncthreads();
        for (int i = tid; i < 4096; i += 256) {
            int c = i >> 8; int mm = i & 255;
            u_s[mm * 20 + c] = g_k[(b * 16 + c) * 1024 + chh * 256 + mm];
        }
        __syncthreads();
        #pragma unroll
        for (int jj = 0; jj < 8; ++jj) {
            int j  = chh * 8 + jj;
            const float* kr = &u_s[(jj * 32 + lane) * 20];
            float a = 0.f, bb2 = 0.f;
            #pragma unroll
            for (int c4 = 0; c4 < 4; ++c4) {
                float4 kv = *reinterpret_cast<const float4*>(kr + c4 * 4);
                a   += q0[c4*4+0]*kv.x + q0[c4*4+1]*kv.y
                     + q0[c4*4+2]*kv.z + q0[c4*4+3]*kv.w;
                bb2 += q1[c4*4+0]*kv.x + q1[c4*4+1]*kv.y
                     + q1[c4*4+2]*kv.z + q1[c4*4+3]*kv.w;
            }
            s0[j] = a; s1[j] = bb2;
        }
    }

    // ---- phase B: softmax over m (registers + warp butterflies) ----
    float m0 = -1e30f, m1 = -1e30f;
    #pragma unroll
    for (int j = 0; j < 32; ++j) { m0 = fmaxf(m0, s0[j]); m1 = fmaxf(m1, s1[j]); }
    #pragma unroll
    for (int o = 16; o > 0; o >>= 1) {
        m0 = fmaxf(m0, __shfl_xor_sync(0xffffffffu, m0, o));
        m1 = fmaxf(m1, __shfl_xor_sync(0xffffffffu, m1, o));
    }
    float sum0 = 0.f, sum1 = 0.f;
    #pragma unroll
    for (int j = 0; j < 32; ++j) {
        s0[j] = __expf(s0[j] - m0); sum0 += s0[j];
        s1[j] = __expf(s1[j] - m1); sum1 += s1[j];
    }
    #pragma unroll
    for (int o = 16; o > 0; o >>= 1) {
        sum0 += __shfl_xor_sync(0xffffffffu, sum0, o);
        sum1 += __shfl_xor_sync(0xffffffffu, sum1, o);
    }
    float inv0 = 1.f / sum0, inv1 = 1.f / sum1;
    #pragma unroll
    for (int j = 0; j < 32; ++j) { s0[j] *= inv0; s1[j] *= inv1; }

    // ---- phase C: z[c][r] = sum_m P[r][m] v[c][m] -------------------------
    // thread = 4 channels x 4 rows x 32-of-128 m per chunk (ms quarter).
    const int ms  = tid >> 6;                // 0..3 (constant per warp)
    const int cg4 = ((tid >> 2) & 15) << 2;  // channel base 0,4,...,60
    const int rg4 = (tid & 3) << 2;          // row base 0,4,8,12
    float zacc[4][4];
    #pragma unroll
    for (int j = 0; j < 4; ++j)
        #pragma unroll
        for (int i = 0; i < 4; ++i) zacc[j][i] = 0.f;

    for (int cm = 0; cm < 8; ++cm) {
        __syncthreads();
        // stage P transposed: P_s[m_local][row], stride 20 (from score regs)
        const int chh2 = cm >> 1, jj0 = (cm & 1) * 4;
        #pragma unroll
        for (int jjl = 0; jjl < 4; ++jjl) {
            int j  = chh2 * 8 + jj0 + jjl;
            int ml = jjl * 32 + lane;
            P_s[ml * 20 + rl]     = s0[j];
            P_s[ml * 20 + rl + 1] = s1[j];
        }
        // stage v: v_s[c][m_local], stride 132 (float4, conflict-free)
        const int mbase = cm * 128;
        #pragma unroll
        for (int r = 0; r < 8; ++r) {
            int q  = tid + r * 256;
            int c  = q >> 5;
            int m4 = (q & 31) << 2;
            float4 vv = *reinterpret_cast<const float4*>(
                &g_v[(b * 64 + c) * 1024 + mbase + m4]);
            *reinterpret_cast<float4*>(&v_s[c * 132 + m4]) = vv;
        }
        __syncthreads();

        const int mb = ms * 32;
        #pragma unroll 4
        for (int mi = 0; mi < 32; ++mi) {
            int m = mb + mi;
            float4 p4 = *reinterpret_cast<const float4*>(&P_s[m * 20 + rg4]);
            #pragma unroll
            for (int j = 0; j < 4; ++j) {
                float vv = v_s[(cg4 + j) * 132 + m];
                zacc[j][0] += vv * p4.x; zacc[j][1] += vv * p4.y;
                zacc[j][2] += vv * p4.z; zacc[j][3] += vv * p4.w;
            }
        }
    }

    // write partials zp[ms][c][r] (stride 16) into u_s, then reduce -> z_s
    __syncthreads();
    #pragma unroll
    for (int j = 0; j < 4; ++j)
        #pragma unroll
        for (int i = 0; i < 4; ++i)
            u_s[ms * 1024 + (cg4 + j) * 16 + rg4 + i] = zacc[j][i];
    __syncthreads();
    #pragma unroll
    for (int i = 0; i < 4; ++i) {
        int o = tid + 256 * i;
        int c = o >> 4, r = o & 15;
        z_s[c * 20 + r] = u_s[o] + u_s[1024 + o] + u_s[2048 + o] + u_s[3072 + o];
    }
    __syncthreads();

    // ---- phase D: attended = z_w @ z + z_b; write out + g_h ----
    for (int i = tid; i < 4096; i += 256) u_s[i] = zw[i];
    __syncthreads();

    const int oc = tid >> 2;
    const int rg = (tid & 3) << 2;
    float a4[4];
    float bv = zb[oc];
    #pragma unroll
    for (int i = 0; i < 4; ++i) a4[i] = bv;
    #pragma unroll 8
    for (int c = 0; c < 64; ++c) {
        float wv = u_s[oc * 64 + c];
        float4 zv = *reinterpret_cast<const float4*>(&z_s[c * 20 + rg]);
        a4[0] += wv * zv.x; a4[1] += wv * zv.y;
        a4[2] += wv * zv.z; a4[3] += wv * zv.w;
    }
    #pragma unroll
    for (int i = 0; i < 4; ++i) {
        int n = n0b + rg + i;
        g_h[(b * 64 + oc) * 1024 + n] = a4[i];
        out[((b * 64 + oc) * 16 + t) * 1024 + n] = a4[i];
    }
}

// ---------------- orchestration --------------------------------------------
extern "C" void kernel_launch(void* const* d_in, const int* in_sizes, int n_in,
                              void* d_out, int out_size)
{
    (void)in_sizes; (void)n_in; (void)out_size;
    const float* X   = (const float*)d_in[0];
    const float* Wc  = (const float*)d_in[1];
    const float* bcc = (const float*)d_in[2];
    const float* Wci = (const float*)d_in[3];
    const float* Wcf = (const float*)d_in[4];
    const float* Wco = (const float*)d_in[5];
    const float* qw  = (const float*)d_in[6];
    const float* qb  = (const float*)d_in[7];
    const float* kw  = (const float*)d_in[8];
    const float* kb  = (const float*)d_in[9];
    const float* vw  = (const float*)d_in[10];
    const float* vb  = (const float*)d_in[11];
    const float* zw  = (const float*)d_in[12];
    const float* zb  = (const float*)d_in[13];
    float* out = (float*)d_out;

    k_init<<<4096, 256>>>();
    for (int t = 0; t < NT; ++t) {
        k_convgate<<<dim3(16, 16),    256>>>(X, Wc, bcc, Wci, Wcf, Wco, t);
        k_qkv     <<<dim3(4, 12, 16), 256>>>(qw, qb, kw, kb, vw, vb);
        k_attn    <<<dim3(64, 16),    256>>>(zw, zb, out, t);
    }
}

// round 7
// speedup vs baseline: 1.4285x; 1.4285x over previous
#include <cuda_runtime.h>
#include <cuda_bf16.h>
#include <math.h>
#include <cstdint>

#define BB 16
#define NT 16

// ---------------- persistent scratch (device globals; no allocation) -------
__device__ float g_h [16*64*1024];     // attended h (recurrent carry)
__device__ float g_hg[16*64*1024];     // pre-attention h (gate output)
__device__ float g_c [16*64*1024];     // cell state
__device__ float g_q [16*16*1024];
__device__ float g_k [16*16*1024];
__device__ float g_v [16*64*1024];
__device__ float g_conv[16*256*1024];  // conv output (B,256,32,32), pre-bias
// bf16 hi/lo split conv weights in mma-fragment-linear order:
// [gate][c0(18)][split(2)][ni(8)][ki(4)][lane(32)][slot(2)] as u32(bf16x2)
__device__ uint32_t g_Wfrag[294912];

// ---------------- init: zero h and c ---------------------------------------
__global__ void k_init()
{
    int i = blockIdx.x * 256 + threadIdx.x;
    g_h[i] = 0.f;
    g_c[i] = 0.f;
}

__device__ __forceinline__ float sigf(float x) { return 1.f / (1.f + __expf(-x)); }
__device__ __forceinline__ float tanh_fast(float x)
{
    return __fdividef(2.f, 1.f + __expf(-2.f * x)) - 1.f;
}
__device__ __forceinline__ uint32_t pack_bf16(float a, float b)
{
    __nv_bfloat162 h2 = __floats2bfloat162_rn(a, b);   // x=a (low), y=b (high)
    return *reinterpret_cast<uint32_t*>(&h2);
}
__device__ __forceinline__ float bf16_lo(float a)
{
    return a - __bfloat162float(__float2bfloat16(a));
}

// ---------------- weight prep: split + fragment-linear layout --------------
// B fragment (m16n8k16, col-major): b_s0 = k{2t,2t+1}, col g; b_s1 = k{2t+8,2t+9}.
__global__ void k_prepw(const float* __restrict__ Wc)
{
    int idx   = blockIdx.x * 256 + threadIdx.x;   // 294912
    int inner = idx & 4095;
    int outer = idx >> 12;                        // 0..71
    int c0    = outer % 18;
    int gate  = outer / 18;
    int s     = inner & 1;
    int lane  = (inner >> 1) & 31;
    int ki    = (inner >> 6) & 3;
    int ni    = (inner >> 8) & 7;
    int sp    = (inner >> 11) & 1;

    int g = lane >> 2, tt = lane & 3;
    int n_global = gate * 64 + ni * 8 + g;
    int k0 = c0 * 64 + ki * 16 + 2 * tt + 8 * s;

    float w0, w1;
    {
        int ci = k0 / 9, r = k0 - ci * 9;
        w0 = Wc[(n_global * 128 + ci) * 9 + r];
        int k1 = k0 + 1;
        ci = k1 / 9; r = k1 - ci * 9;
        w1 = Wc[(n_global * 128 + ci) * 9 + r];
    }
    if (sp == 1) { w0 = bf16_lo(w0); w1 = bf16_lo(w1); }
    g_Wfrag[idx] = pack_bf16(w0, w1);
}

// ---------------- conv via mma.sync bf16 (HMMA fallback path) --------------
// grid (8 m-tiles of 128 pixels, 16 batch, 4 gates), 256 threads = 8 warps.
// D[m=pixel][n=cout] = sum_k A[m][k]*B[n][k]; K=1152 in 18 chunks of 64.
__device__ __forceinline__ void mma_bf16(float* c, uint4 a, uint2 b)
{
    asm volatile(
        "mma.sync.aligned.m16n8k16.row.col.f32.bf16.bf16.f32 "
        "{%0,%1,%2,%3}, {%4,%5,%6,%7}, {%8,%9}, {%0,%1,%2,%3};"
        : "+f"(c[0]), "+f"(c[1]), "+f"(c[2]), "+f"(c[3])
        : "r"(a.x), "r"(a.y), "r"(a.z), "r"(a.w), "r"(b.x), "r"(b.y));
}

__global__ void __launch_bounds__(256, 2) k_conv_mma(
    const float* __restrict__ X, int t)
{
    // smem union: [A 4096u | Bh 2048u | Bl 2048u] = 8192 u32; epilogue 8448 fl
    __shared__ uint32_t sm_u[8448];               // 33 KB
    uint32_t* A_s  = sm_u;
    uint32_t* Bh_s = sm_u + 4096;
    uint32_t* Bl_s = sm_u + 6144;

    const int tid  = threadIdx.x;
    const int wid  = tid >> 5;
    const int lane = tid & 31;
    const int mt   = blockIdx.x;
    const int b    = blockIdx.y;
    const int gate = blockIdx.z;
    const int n0   = gate * 64;
    const int wm   = wid >> 1;                    // 0..3 -> m16 tiles wm*2,+1
    const int wn   = wid & 1;                     // 0..1 -> n8 tiles wn*4..+3
    const int g    = lane >> 2, tt = lane & 3;

    const float* Xb = X + (b * 64 * 16 + t) * 1024;   // + ci*16*1024
    const float* Hb = g_h + b * 64 * 1024;

    float acc[2][4][4];
    #pragma unroll
    for (int im = 0; im < 2; ++im)
        #pragma unroll
        for (int in = 0; in < 4; ++in)
            #pragma unroll
            for (int q = 0; q < 4; ++q) acc[im][in][q] = 0.f;

    float av[32];
    const uint4* A4  = reinterpret_cast<const uint4*>(A_s);
    const uint2* Bh2 = reinterpret_cast<const uint2*>(Bh_s);
    const uint2* Bl2 = reinterpret_cast<const uint2*>(Bl_s);

    for (int c0 = 0; c0 < 18; ++c0) {
        // ---- stage A hi (im2col gather in fragment-linear order) ----
        #pragma unroll
        for (int j = 0; j < 16; ++j) {
            int slot = j * 256 + tid;
            int s  = slot & 3;
            int ln = (slot >> 2) & 31;
            int ki = (slot >> 7) & 3;
            int mi = slot >> 9;
            int gg = ln >> 2, t4 = ln & 3;
            int m  = mi * 16 + gg + 8 * (s & 1);
            int kb = c0 * 64 + ki * 16 + 2 * t4 + 8 * (s >> 1);
            int pix = mt * 128 + m;
            int py = pix >> 5, px = pix & 31;
            float a0 = 0.f, a1 = 0.f;
            #pragma unroll
            for (int h = 0; h < 2; ++h) {
                int kg = kb + h;
                int ci = kg / 9, r = kg - ci * 9;
                int dy = r / 3 - 1, dx = r - (r / 3) * 3 - 1;
                int ys = py + dy, xs = px + dx;
                float a = 0.f;
                if ((unsigned)ys < 32u && (unsigned)xs < 32u) {
                    int sp2 = ys * 32 + xs;
                    a = (ci < 64) ? Xb[ci * 16384 + sp2]
                                  : Hb[(ci - 64) * 1024 + sp2];
                }
                if (h == 0) a0 = a; else a1 = a;
            }
            av[2 * j] = a0; av[2 * j + 1] = a1;
            A_s[slot] = pack_bf16(a0, a1);
        }
        // ---- stage Bh, Bl (contiguous copies from prepared weights) ----
        {
            const uint4* src = reinterpret_cast<const uint4*>(
                g_Wfrag + (gate * 18 + c0) * 4096);
            uint4* dh = reinterpret_cast<uint4*>(Bh_s);
            uint4* dl = reinterpret_cast<uint4*>(Bl_s);
            dh[tid]       = src[tid];
            dh[tid + 256] = src[tid + 256];
            dl[tid]       = src[tid + 512];
            dl[tid + 256] = src[tid + 768];
        }
        __syncthreads();

        // ---- pass 1: Ah*Bh + Ah*Bl ----
        #pragma unroll
        for (int ki = 0; ki < 4; ++ki) {
            uint4 af0 = A4[((wm * 2    ) * 4 + ki) * 32 + lane];
            uint4 af1 = A4[((wm * 2 + 1) * 4 + ki) * 32 + lane];
            #pragma unroll
            for (int in = 0; in < 4; ++in) {
                int ni = wn * 4 + in;
                uint2 bh = Bh2[(ni * 4 + ki) * 32 + lane];
                uint2 bl = Bl2[(ni * 4 + ki) * 32 + lane];
                mma_bf16(acc[0][in], af0, bh);
                mma_bf16(acc[1][in], af1, bh);
                mma_bf16(acc[0][in], af0, bl);
                mma_bf16(acc[1][in], af1, bl);
            }
        }
        __syncthreads();

        // ---- restage A with lo parts (from registers) ----
        #pragma unroll
        for (int j = 0; j < 16; ++j) {
            int slot = j * 256 + tid;
            A_s[slot] = pack_bf16(bf16_lo(av[2 * j]), bf16_lo(av[2 * j + 1]));
        }
        __syncthreads();

        // ---- pass 2: Al*Bh ----
        #pragma unroll
        for (int ki = 0; ki < 4; ++ki) {
            uint4 af0 = A4[((wm * 2    ) * 4 + ki) * 32 + lane];
            uint4 af1 = A4[((wm * 2 + 1) * 4 + ki) * 32 + lane];
            #pragma unroll
            for (int in = 0; in < 4; ++in) {
                int ni = wn * 4 + in;
                uint2 bh = Bh2[(ni * 4 + ki) * 32 + lane];
                mma_bf16(acc[0][in], af0, bh);
                mma_bf16(acc[1][in], af1, bh);
            }
        }
        __syncthreads();
    }

    // ---- epilogue: C frags -> smem [n][m] (pad 132) -> coalesced g_conv ----
    float* out_s = reinterpret_cast<float*>(sm_u);
    #pragma unroll
    for (int im = 0; im < 2; ++im) {
        int mi = wm * 2 + im;
        int m  = mi * 16 + g;
        #pragma unroll
        for (int in = 0; in < 4; ++in) {
            int ni = wn * 4 + in;
            int n  = ni * 8 + 2 * tt;
            out_s[ n      * 132 + m    ] = acc[im][in][0];
            out_s[(n + 1) * 132 + m    ] = acc[im][in][1];
            out_s[ n      * 132 + m + 8] = acc[im][in][2];
            out_s[(n + 1) * 132 + m + 8] = acc[im][in][3];
        }
    }
    __syncthreads();
    #pragma unroll
    for (int j = 0; j < 32; ++j) {
        int idx = j * 256 + tid;
        int n = idx >> 7, m = idx & 127;
        g_conv[(b * 256 + n0 + n) * 1024 + mt * 128 + m] = out_s[n * 132 + m];
    }
}

// ---------------- ConvLSTM gating (elementwise, peephole; adds bias) -------
__global__ void k_gate(const float* __restrict__ bc,
                       const float* __restrict__ Wci,
                       const float* __restrict__ Wcf,
                       const float* __restrict__ Wco)
{
    int idx = blockIdx.x * 256 + threadIdx.x;
    int b   = idx >> 16;
    int c   = (idx >> 10) & 63;
    int pos = idx & 1023;
    int cb  = (b * 256 + c) * 1024 + pos;

    float ic = g_conv[cb]              + bc[c];
    float fc = g_conv[cb + 64 * 1024]  + bc[64 + c];
    float gc = g_conv[cb + 128 * 1024] + bc[128 + c];
    float oc = g_conv[cb + 192 * 1024] + bc[192 + c];
    float cp = g_c[idx];
    int   wp = c * 1024 + pos;

    float i  = sigf(ic + Wci[wp] * cp);
    float f  = sigf(fc + Wcf[wp] * cp);
    float nc = f * cp + i * tanh_fast(gc);
    float o  = sigf(oc + Wco[wp] * nc);
    g_c[idx]  = nc;
    g_hg[idx] = o * tanh_fast(nc);
}

// ---------------- q,k,v 1x1 convs: 96 output ch from 64 --------------------
__global__ void k_qkv(const float* __restrict__ qw, const float* __restrict__ qb,
                      const float* __restrict__ kw, const float* __restrict__ kb,
                      const float* __restrict__ vw, const float* __restrict__ vb)
{
    __shared__ float h_s[32 * 256];
    __shared__ float w_s[8 * 64];

    const int p0  = blockIdx.x * 256;
    const int oc0 = blockIdx.y * 8;
    const int b   = blockIdx.z;
    const int tid = threadIdx.x;

    for (int i = tid; i < 512; i += 256) {
        int j = i >> 6; int c = i & 63; int oc = oc0 + j;
        w_s[i] = (oc < 16) ? qw[oc * 64 + c]
               : (oc < 32) ? kw[(oc - 16) * 64 + c]
                           : vw[(oc - 32) * 64 + c];
    }

    float acc[8];
    #pragma unroll
    for (int j = 0; j < 8; ++j) {
        int oc = oc0 + j;
        acc[j] = (oc < 16) ? qb[oc] : (oc < 32) ? kb[oc - 16] : vb[oc - 32];
    }

    for (int chh = 0; chh < 2; ++chh) {
        __syncthreads();
        for (int i = tid; i < 8192; i += 256) {
            int c = i >> 8; int j = i & 255;
            h_s[i] = g_hg[(b * 64 + chh * 32 + c) * 1024 + p0 + j];
        }
        __syncthreads();
        #pragma unroll 8
        for (int c = 0; c < 32; ++c) {
            float hv = h_s[c * 256 + tid];
            #pragma unroll
            for (int j = 0; j < 8; ++j)
                acc[j] += w_s[j * 64 + chh * 32 + c] * hv;
        }
    }

    int pos = p0 + tid;
    #pragma unroll
    for (int j = 0; j < 8; ++j) {
        int oc = oc0 + j;
        if (oc < 16)      g_q[(b * 16 + oc) * 1024 + pos]        = acc[j];
        else if (oc < 32) g_k[(b * 16 + (oc - 16)) * 1024 + pos] = acc[j];
        else              g_v[(b * 64 + (oc - 32)) * 1024 + pos] = acc[j];
    }
}

// ---------------- fused attention (R3 version) -----------------------------
__global__ void __launch_bounds__(256, 2) k_attn(
    const float* __restrict__ zw, const float* __restrict__ zb,
    float* __restrict__ out, int t)
{
    __shared__ float u_s[8192];
    __shared__ float z_s[64 * 16];

    const int b    = blockIdx.y;
    const int n0   = blockIdx.x * 16;
    const int tid  = threadIdx.x;
    const int w    = tid >> 5;
    const int lane = tid & 31;
    const int rl   = w * 2;
    const int r0   = n0 + rl;

    float q0[16], q1[16];
    #pragma unroll
    for (int c = 0; c < 16; ++c) {
        q0[c] = g_q[(b * 16 + c) * 1024 + r0];
        q1[c] = g_q[(b * 16 + c) * 1024 + r0 + 1];
    }

    float s0[32], s1[32];
    for (int chh = 0; chh < 4; ++chh) {
        __syncthreads();
        for (int i = tid; i < 4096; i += 256) {
            int c = i >> 8; int mm = i & 255;
            u_s[i] = g_k[(b * 16 + c) * 1024 + chh * 256 + mm];
        }
        __syncthreads();
        #pragma unroll
        for (int jj = 0; jj < 8; ++jj) {
            int j  = chh * 8 + jj;
            int mm = jj * 32 + lane;
            float a = 0.f, bb2 = 0.f;
            #pragma unroll
            for (int c = 0; c < 16; ++c) {
                float kv = u_s[c * 256 + mm];
                a   += q0[c] * kv;
                bb2 += q1[c] * kv;
            }
            s0[j] = a; s1[j] = bb2;
        }
    }

    float m0 = -1e30f, m1 = -1e30f;
    #pragma unroll
    for (int j = 0; j < 32; ++j) { m0 = fmaxf(m0, s0[j]); m1 = fmaxf(m1, s1[j]); }
    #pragma unroll
    for (int o = 16; o > 0; o >>= 1) {
        m0 = fmaxf(m0, __shfl_xor_sync(0xffffffffu, m0, o));
        m1 = fmaxf(m1, __shfl_xor_sync(0xffffffffu, m1, o));
    }
    float sum0 = 0.f, sum1 = 0.f;
    #pragma unroll
    for (int j = 0; j < 32; ++j) {
        s0[j] = __expf(s0[j] - m0); sum0 += s0[j];
        s1[j] = __expf(s1[j] - m1); sum1 += s1[j];
    }
    #pragma unroll
    for (int o = 16; o > 0; o >>= 1) {
        sum0 += __shfl_xor_sync(0xffffffffu, sum0, o);
        sum1 += __shfl_xor_sync(0xffffffffu, sum1, o);
    }
    float inv0 = 1.f / sum0, inv1 = 1.f / sum1;
    #pragma unroll
    for (int j = 0; j < 32; ++j) { s0[j] *= inv0; s1[j] *= inv1; }

    for (int cc8 = 0; cc8 < 64; cc8 += 8) {
        __syncthreads();
        for (int i = tid; i < 8192; i += 256) {
            int c = i >> 10; int mm = i & 1023;
            u_s[i] = g_v[(b * 64 + cc8 + c) * 1024 + mm];
        }
        __syncthreads();

        float a0[8], a1[8];
        #pragma unroll
        for (int c = 0; c < 8; ++c) { a0[c] = 0.f; a1[c] = 0.f; }
        #pragma unroll
        for (int j = 0; j < 32; ++j) {
            int moff = ((j >> 3) << 8) + ((j & 7) << 5) + lane;
            float p0v = s0[j], p1v = s1[j];
            #pragma unroll
            for (int c = 0; c < 8; ++c) {
                float vv = u_s[c * 1024 + moff];
                a0[c] += p0v * vv;
                a1[c] += p1v * vv;
            }
        }
        #pragma unroll
        for (int c = 0; c < 8; ++c) {
            #pragma unroll
            for (int o = 16; o > 0; o >>= 1) {
                a0[c] += __shfl_xor_sync(0xffffffffu, a0[c], o);
                a1[c] += __shfl_xor_sync(0xffffffffu, a1[c], o);
            }
        }
        float out_v = 0.f;
        #pragma unroll
        for (int c = 0; c < 8; ++c) {
            if (lane == c)     out_v = a0[c];
            if (lane == c + 8) out_v = a1[c];
        }
        if (lane < 16) {
            int row = rl + (lane >> 3);
            int chn = cc8 + (lane & 7);
            z_s[chn * 16 + row] = out_v;
        }
    }

    __syncthreads();
    for (int i = tid; i < 4096; i += 256) u_s[i] = zw[i];
    __syncthreads();

    const int oc = tid >> 2;
    const int rg = (tid & 3) << 2;
    float a4[4];
    float bv = zb[oc];
    #pragma unroll
    for (int i = 0; i < 4; ++i) a4[i] = bv;
    #pragma unroll 8
    for (int c = 0; c < 64; ++c) {
        float wv = u_s[oc * 64 + c];
        float4 zv = *reinterpret_cast<const float4*>(&z_s[c * 16 + rg]);
        a4[0] += wv * zv.x; a4[1] += wv * zv.y;
        a4[2] += wv * zv.z; a4[3] += wv * zv.w;
    }
    #pragma unroll
    for (int i = 0; i < 4; ++i) {
        int n = n0 + rg + i;
        g_h[(b * 64 + oc) * 1024 + n] = a4[i];
        out[((b * 64 + oc) * 16 + t) * 1024 + n] = a4[i];
    }
}

// ---------------- orchestration --------------------------------------------
extern "C" void kernel_launch(void* const* d_in, const int* in_sizes, int n_in,
                              void* d_out, int out_size)
{
    (void)in_sizes; (void)n_in; (void)out_size;
    const float* X   = (const float*)d_in[0];
    const float* Wc  = (const float*)d_in[1];
    const float* bcc = (const float*)d_in[2];
    const float* Wci = (const float*)d_in[3];
    const float* Wcf = (const float*)d_in[4];
    const float* Wco = (const float*)d_in[5];
    const float* qw  = (const float*)d_in[6];
    const float* qb  = (const float*)d_in[7];
    const float* kw  = (const float*)d_in[8];
    const float* kb  = (const float*)d_in[9];
    const float* vw  = (const float*)d_in[10];
    const float* vb  = (const float*)d_in[11];
    const float* zw  = (const float*)d_in[12];
    const float* zb  = (const float*)d_in[13];
    float* out = (float*)d_out;

    k_init <<<4096, 256>>>();
    k_prepw<<<1152, 256>>>(Wc);
    for (int t = 0; t < NT; ++t) {
        k_conv_mma<<<dim3(8, 16, 4),  256>>>(X, t);
        k_gate    <<<4096,            256>>>(bcc, Wci, Wcf, Wco);
        k_qkv     <<<dim3(4, 12, 16), 256>>>(qw, qb, kw, kb, vw, vb);
        k_attn    <<<dim3(64, 16),    256>>>(zw, zb, out, t);
    }
}